// round 2
// baseline (speedup 1.0000x reference)
#include <cuda_runtime.h>

// Pendulum2 constrained-dynamics RHS, closed form. 2 rows per thread,
// front-batched 128-bit loads (MLP=4), streaming cache hints (no reuse).
//
// Derivation (M0=M1=10, G=10):
//   det' = 2 s1 s2 - c^2 = s1 s2 + u^2   (u = x0 dy - x1 dx; cancellation-free)
//   R1 = -20 x1 + 2|v01|^2 ; R2 = 2|dv|^2 ; lam = 2.5 adj(L')R/det'

__device__ __forceinline__ float4 ldcs4(const float4* p) {
    float4 v;
    asm volatile("ld.global.cs.v4.f32 {%0,%1,%2,%3}, [%4];"
                 : "=f"(v.x), "=f"(v.y), "=f"(v.z), "=f"(v.w) : "l"(p));
    return v;
}
__device__ __forceinline__ void stcs4(float4* p, float4 v) {
    asm volatile("st.global.cs.v4.f32 [%0], {%1,%2,%3,%4};"
                 :: "l"(p), "f"(v.x), "f"(v.y), "f"(v.z), "f"(v.w) : "memory");
}

__device__ __forceinline__ float4 accel(const float4& X, const float4& V) {
    float dx  = X.x - X.z;
    float dy  = X.y - X.w;
    float dv0 = V.x - V.z;
    float dv1 = V.y - V.w;

    float s1 = fmaf(X.x, X.x, X.y * X.y);
    float s2 = fmaf(dx, dx, dy * dy);
    float c  = fmaf(X.x, dx, X.y * dy);
    float u  = fmaf(X.x, dy, -(X.y * dx));

    float R1 = fmaf(2.0f, fmaf(V.x, V.x, V.y * V.y), -20.0f * X.y);
    float R2 = 2.0f * fmaf(dv0, dv0, dv1 * dv1);

    float det = fmaf(s1, s2, u * u);   // = 2*s1*s2 - c^2, stable form
    float inv = 2.5f / det;

    float lam1 = fmaf(2.0f * s2, R1, -(c * R2)) * inv;
    float lam2 = fmaf(s1, R2, -(c * R1)) * inv;

    float4 A;
    A.x = -0.2f * fmaf(X.x, lam1, dx * lam2);
    A.y = fmaf(-0.2f, fmaf(X.y, lam1, dy * lam2), -10.0f);
    A.z = 0.2f * (dx * lam2);
    A.w = fmaf(0.2f, dy * lam2, -10.0f);
    return A;
}

__global__ void __launch_bounds__(256)
pendulum2_kernel(const float4* __restrict__ in4, float4* __restrict__ out4, int bs)
{
    int i = blockIdx.x * blockDim.x + threadIdx.x;   // handles rows 2i, 2i+1
    int r0 = 2 * i;
    if (r0 + 1 >= bs) {
        if (r0 < bs) {   // tail row (bs odd — not hit for 2M but keep safe)
            float4 X = ldcs4(&in4[2 * r0]);
            float4 V = ldcs4(&in4[2 * r0 + 1]);
            stcs4(&out4[2 * r0], V);
            stcs4(&out4[2 * r0 + 1], accel(X, V));
        }
        return;
    }

    // 4 consecutive float4s per thread: batch all loads up front (MLP=4)
    const float4* p = &in4[4 * i];
    float4 X0 = ldcs4(p + 0);
    float4 V0 = ldcs4(p + 1);
    float4 X1 = ldcs4(p + 2);
    float4 V1 = ldcs4(p + 3);

    float4 A0 = accel(X0, V0);
    float4 A1 = accel(X1, V1);

    float4* q = &out4[4 * i];
    stcs4(q + 0, V0);
    stcs4(q + 1, A0);
    stcs4(q + 2, V1);
    stcs4(q + 3, A1);
}

extern "C" void kernel_launch(void* const* d_in, const int* in_sizes, int n_in,
                              void* d_out, int out_size)
{
    // inputs (metadata order): t (1,), coords (bs, 8)
    const float* coords = (const float*)d_in[1];
    int bs = in_sizes[1] / 8;

    const float4* in4 = (const float4*)coords;
    float4* out4      = (float4*)d_out;

    int threads = 256;
    int pairs   = (bs + 1) / 2;
    int blocks  = (pairs + threads - 1) / threads;
    pendulum2_kernel<<<blocks, threads>>>(in4, out4, bs);
}

// round 3
// speedup vs baseline: 1.1581x; 1.1581x over previous
#include <cuda_runtime.h>

// Pendulum2 constrained-dynamics RHS, closed form.
// R1 layout (32B/thread-row, default caching — L2-resident reuse across
// replays) + MLP=4: each thread handles rows i and i+half, loads batched.
//
//   det' = 2 s1 s2 - c^2 = s1 s2 + u^2   (u = x0 dy - x1 dx; cancellation-free)
//   R1 = -20 x1 + 2|v01|^2 ; R2 = 2|dv|^2 ; lam = 2.5 adj(L')R/det'

__device__ __forceinline__ float4 accel(const float4& X, const float4& V) {
    float dx  = X.x - X.z;
    float dy  = X.y - X.w;
    float dv0 = V.x - V.z;
    float dv1 = V.y - V.w;

    float s1 = fmaf(X.x, X.x, X.y * X.y);
    float s2 = fmaf(dx, dx, dy * dy);
    float c  = fmaf(X.x, dx, X.y * dy);
    float u  = fmaf(X.x, dy, -(X.y * dx));

    float R1 = fmaf(2.0f, fmaf(V.x, V.x, V.y * V.y), -20.0f * X.y);
    float R2 = 2.0f * fmaf(dv0, dv0, dv1 * dv1);

    float det = fmaf(s1, s2, u * u);   // = 2*s1*s2 - c^2, stable form
    float inv = 2.5f / det;

    float lam1 = fmaf(2.0f * s2, R1, -(c * R2)) * inv;
    float lam2 = fmaf(s1, R2, -(c * R1)) * inv;

    float4 A;
    A.x = -0.2f * fmaf(X.x, lam1, dx * lam2);
    A.y = fmaf(-0.2f, fmaf(X.y, lam1, dy * lam2), -10.0f);
    A.z = 0.2f * (dx * lam2);
    A.w = fmaf(0.2f, dy * lam2, -10.0f);
    return A;
}

__global__ void __launch_bounds__(256)
pendulum2_kernel(const float4* __restrict__ in4, float4* __restrict__ out4,
                 int bs, int half)
{
    int i = blockIdx.x * blockDim.x + threadIdx.x;
    if (i >= half) return;
    int j = i + half;

    // Front-batch all loads: two independent rows, R1-style 32B stride each.
    float4 X0 = in4[2 * i];
    float4 V0 = in4[2 * i + 1];
    float4 X1, V1;
    bool has_j = (j < bs);
    if (has_j) {
        X1 = in4[2 * j];
        V1 = in4[2 * j + 1];
    }

    float4 A0 = accel(X0, V0);
    out4[2 * i]     = V0;
    out4[2 * i + 1] = A0;

    if (has_j) {
        float4 A1 = accel(X1, V1);
        out4[2 * j]     = V1;
        out4[2 * j + 1] = A1;
    }
}

extern "C" void kernel_launch(void* const* d_in, const int* in_sizes, int n_in,
                              void* d_out, int out_size)
{
    // inputs (metadata order): t (1,), coords (bs, 8)
    const float* coords = (const float*)d_in[1];
    int bs = in_sizes[1] / 8;
    int half = (bs + 1) / 2;

    const float4* in4 = (const float4*)coords;
    float4* out4      = (float4*)d_out;

    int threads = 256;
    int blocks  = (half + threads - 1) / threads;
    pendulum2_kernel<<<blocks, threads>>>(in4, out4, bs, half);
}

// round 4
// speedup vs baseline: 1.2575x; 1.0858x over previous
#include <cuda_runtime.h>
#include <cstdint>

// Pendulum2 constrained-dynamics RHS, closed form.
// One row (32B) per thread via Blackwell 256-bit ld/st (ld.global.v8.b32):
// each warp-wide load/store covers 1KB fully dense (8 lines @ 100%),
// halving memory instruction count and L1 wavefronts vs float4 pairs.
//
//   det' = 2 s1 s2 - c^2 = s1 s2 + u^2   (u = x0 dy - x1 dx; cancellation-free)
//   R1 = -20 x1 + 2|v01|^2 ; R2 = 2|dv|^2 ; lam = 2.5 adj(L')R/det'

__global__ void __launch_bounds__(256)
pendulum2_kernel(const float* __restrict__ in, float* __restrict__ out, int bs)
{
    int i = blockIdx.x * blockDim.x + threadIdx.x;
    if (i >= bs) return;

    const float* p = in + 8u * (uint32_t)i;
    uint32_t r0, r1, r2, r3, r4, r5, r6, r7;
    asm("ld.global.v8.b32 {%0,%1,%2,%3,%4,%5,%6,%7}, [%8];"
        : "=r"(r0), "=r"(r1), "=r"(r2), "=r"(r3),
          "=r"(r4), "=r"(r5), "=r"(r6), "=r"(r7)
        : "l"(p));

    float x0 = __uint_as_float(r0), x1 = __uint_as_float(r1);
    float x2 = __uint_as_float(r2), x3 = __uint_as_float(r3);
    float v0 = __uint_as_float(r4), v1 = __uint_as_float(r5);
    float v2 = __uint_as_float(r6), v3 = __uint_as_float(r7);

    float dx  = x0 - x2;
    float dy  = x1 - x3;
    float dv0 = v0 - v2;
    float dv1 = v1 - v3;

    float s1 = fmaf(x0, x0, x1 * x1);
    float s2 = fmaf(dx, dx, dy * dy);
    float c  = fmaf(x0, dx, x1 * dy);
    float u  = fmaf(x0, dy, -(x1 * dx));

    float R1 = fmaf(2.0f, fmaf(v0, v0, v1 * v1), -20.0f * x1);
    float R2 = 2.0f * fmaf(dv0, dv0, dv1 * dv1);

    float det = fmaf(s1, s2, u * u);   // = 2*s1*s2 - c^2, stable form
    float inv = 2.5f / det;

    float lam1 = fmaf(2.0f * s2, R1, -(c * R2)) * inv;
    float lam2 = fmaf(s1, R2, -(c * R1)) * inv;

    float a0 = -0.2f * fmaf(x0, lam1, dx * lam2);
    float a1 = fmaf(-0.2f, fmaf(x1, lam1, dy * lam2), -10.0f);
    float a2 = 0.2f * (dx * lam2);
    float a3 = fmaf(0.2f, dy * lam2, -10.0f);

    float* q = out + 8u * (uint32_t)i;
    asm volatile("st.global.v8.b32 [%0], {%1,%2,%3,%4,%5,%6,%7,%8};"
                 :: "l"(q),
                    "r"(__float_as_uint(v0)), "r"(__float_as_uint(v1)),
                    "r"(__float_as_uint(v2)), "r"(__float_as_uint(v3)),
                    "r"(__float_as_uint(a0)), "r"(__float_as_uint(a1)),
                    "r"(__float_as_uint(a2)), "r"(__float_as_uint(a3))
                 : "memory");
}

extern "C" void kernel_launch(void* const* d_in, const int* in_sizes, int n_in,
                              void* d_out, int out_size)
{
    // inputs (metadata order): t (1,), coords (bs, 8)
    const float* coords = (const float*)d_in[1];
    int bs = in_sizes[1] / 8;

    int threads = 256;
    int blocks  = (bs + threads - 1) / threads;
    pendulum2_kernel<<<blocks, threads>>>(coords, (float*)d_out, bs);
}